// round 1
// baseline (speedup 1.0000x reference)
#include <cuda_runtime.h>
#include <math.h>
#include <float.h>

// Problem constants
#define LSEQ   2048
#define DMODEL 1024
#define NHEAD  16
#define HSZ    64
#define BATCH  4
#define MTOT   (BATCH*LSEQ)      // 8192

// Scratch (device globals: allocation-free rule)
__device__ float g_qkv[(size_t)MTOT * 3 * DMODEL];   // [8192][3072]
__device__ float g_y[(size_t)MTOT * DMODEL];         // [8192][1024]

// ---------------------------------------------------------------------------
// GEMM: C[M,N] = A[M,K] @ B[K,N] + bias[N]
// 128x128 block tile, BK=8, 256 threads, 8x8 micro-tile per thread.
// M,N,K all divisible by 128/8 for our shapes.
// ---------------------------------------------------------------------------
__global__ __launch_bounds__(256, 2) void sgemm_bias_kernel(
    const float* __restrict__ A, const float* __restrict__ B,
    const float* __restrict__ bias, float* __restrict__ C,
    int M, int N, int K)
{
    __shared__ float As[8][128];   // [k][m] (transposed stage)
    __shared__ float Bs[8][128];   // [k][n]

    const int tid  = threadIdx.x;
    const int row0 = blockIdx.y * 128;
    const int col0 = blockIdx.x * 128;
    const int tr   = (tid >> 4) * 8;      // 0..120
    const int tc   = (tid & 15) * 8;      // 0..120

    // A-tile loader: 128 rows x 8 cols = 256 float4 (2 per row)
    const int arow = tid >> 1;            // 0..127
    const int acol = (tid & 1) * 4;       // 0 or 4
    // B-tile loader: 8 rows x 128 cols = 256 float4
    const int brow = tid >> 5;            // 0..7
    const int bcol = (tid & 31) * 4;      // 0..124

    const float* Aptr = A + (size_t)(row0 + arow) * K + acol;
    const float* Bptr = B + (size_t)brow * N + col0 + bcol;

    float acc[8][8];
    #pragma unroll
    for (int i = 0; i < 8; i++)
        #pragma unroll
        for (int j = 0; j < 8; j++) acc[i][j] = 0.f;

    for (int kt = 0; kt < K; kt += 8) {
        const float4 av = *(const float4*)(Aptr + kt);
        const float4 bv = *(const float4*)(Bptr + (size_t)kt * N);
        __syncthreads();
        As[acol + 0][arow] = av.x;
        As[acol + 1][arow] = av.y;
        As[acol + 2][arow] = av.z;
        As[acol + 3][arow] = av.w;
        *(float4*)&Bs[brow][bcol] = bv;
        __syncthreads();
        #pragma unroll
        for (int kk = 0; kk < 8; kk++) {
            float a[8], b[8];
            *(float4*)&a[0] = *(const float4*)&As[kk][tr];
            *(float4*)&a[4] = *(const float4*)&As[kk][tr + 4];
            *(float4*)&b[0] = *(const float4*)&Bs[kk][tc];
            *(float4*)&b[4] = *(const float4*)&Bs[kk][tc + 4];
            #pragma unroll
            for (int i = 0; i < 8; i++)
                #pragma unroll
                for (int j = 0; j < 8; j++)
                    acc[i][j] += a[i] * b[j];
        }
    }

    #pragma unroll
    for (int i = 0; i < 8; i++) {
        float* Cp = C + (size_t)(row0 + tr + i) * N + col0 + tc;
        #pragma unroll
        for (int j = 0; j < 8; j += 4) {
            float4 o;
            o.x = acc[i][j + 0] + bias[col0 + tc + j + 0];
            o.y = acc[i][j + 1] + bias[col0 + tc + j + 1];
            o.z = acc[i][j + 2] + bias[col0 + tc + j + 2];
            o.w = acc[i][j + 3] + bias[col0 + tc + j + 3];
            *(float4*)(Cp + j) = o;
        }
    }
}

// ---------------------------------------------------------------------------
// Fused flash attention with relative position (Music-Transformer skew).
// Srel[l,m] = q_l . Er[L-1-(l-m)]  for the causal part (m <= l).
// One CTA = (batch b, head h, 64-row query block qb). 256 threads.
// For each 64-col key tile: S = Q K^T (64x64), T = Q Er_band^T (64x127),
// combine Srel[i][j] = T[i][i-j+63], online softmax (base-2), O += P V.
// ---------------------------------------------------------------------------
#define SS 68    // stride for 64-wide smem tiles (float4-aligned, conflict-padded)
#define TS 132   // stride for 128-wide tiles
#define ATTN_SMEM_FLOATS (4*64*SS + 2*64*TS + 3*64)
#define ATTN_SMEM_BYTES  (ATTN_SMEM_FLOATS * 4)

__global__ __launch_bounds__(256, 1) void attn_relpos_kernel(
    const float* __restrict__ qkv,   // [8192][3072] : q|k|v
    const float* __restrict__ Er,    // [2048][64]
    float* __restrict__ Y)           // [8192][1024]
{
    extern __shared__ float sm[];
    float* Qsm = sm;                 // [k][i]  64xSS
    float* Ksm = Qsm + 64 * SS;      // [k][j]
    float* Vsm = Ksm + 64 * SS;      // [j][k]
    float* Ssm = Vsm + 64 * SS;      // [j][i]  (scores, then P)
    float* ErT = Ssm + 64 * SS;      // [k][t]  64xTS (t in [0,127))
    float* Tsm = ErT + 64 * TS;      // [i][t]  64xTS
    float* msm = Tsm + 64 * TS;      // [64] running row max (base-2 domain)
    float* lsm = msm + 64;           // [64] running row sum
    float* rsc = lsm + 64;           // [64] row rescale factor

    const int tid = threadIdx.x;
    const int qb  = blockIdx.x & 31;
    const int h   = (blockIdx.x >> 5) & 15;
    const int b   = blockIdx.x >> 9;
    const int l0  = qb * 64;

    const float* qbase = qkv + (size_t)(b * LSEQ) * 3072 + h * HSZ;
    const float* kbase = qbase + DMODEL;
    const float* vbase = qbase + 2 * DMODEL;

    // Load Q tile (transposed: Qsm[k][i])
    for (int idx = tid; idx < 64 * 64; idx += 256) {
        const int i = idx >> 6, k = idx & 63;
        Qsm[k * SS + i] = qbase[(size_t)(l0 + i) * 3072 + k];
    }
    if (tid < 64) { msm[tid] = -1e30f; lsm[tid] = 0.f; }

    float O[4][4];
    #pragma unroll
    for (int a = 0; a < 4; a++)
        #pragma unroll
        for (int c = 0; c < 4; c++) O[a][c] = 0.f;

    const int si = (tid >> 4) * 4;   // micro-tile rows (i)
    const int sj = (tid & 15) * 4;   // micro-tile cols (j / d)
    const int tt = (tid & 15) * 8;   // T-pass cols (t)

    // scale * log2(e): softmax done in base 2
    const float sc2 = 0.125f * 1.4426950408889634f;

    for (int kb = 0; kb <= qb; kb++) {
        const int m0 = kb * 64;
        const int d0 = l0 - m0;
        __syncthreads();   // previous iteration finished reading smem

        // Load K (transposed), V (natural)
        for (int idx = tid; idx < 64 * 64; idx += 256) {
            const int j = idx >> 6, k = idx & 63;
            const float kvv = kbase[(size_t)(m0 + j) * 3072 + k];
            const float vvv = vbase[(size_t)(m0 + j) * 3072 + k];
            Ksm[k * SS + j] = kvv;
            Vsm[j * SS + k] = vvv;
        }
        // Load Er band transposed: ErT[k][t], t=0..126 maps to rel r=d0-63+t,
        // global Er row g = L-1-r = (L+62-d0)-t ; out-of-range -> 0 (masked anyway)
        for (int idx = tid; idx < 127 * 64; idx += 256) {
            const int t = idx >> 6, k = idx & 63;
            const int g = (LSEQ + 62 - d0) - t;
            ErT[k * TS + t] = (g >= 0 && g < LSEQ) ? Er[(size_t)g * HSZ + k] : 0.f;
        }
        __syncthreads();

        // ---- fused S (QK^T) and T (Q ErBand^T) pass ----
        {
            float acc[4][4];
            float accT[4][8];
            #pragma unroll
            for (int a = 0; a < 4; a++) {
                #pragma unroll
                for (int c = 0; c < 4; c++) acc[a][c] = 0.f;
                #pragma unroll
                for (int c = 0; c < 8; c++) accT[a][c] = 0.f;
            }
            #pragma unroll 4
            for (int kk = 0; kk < 64; kk++) {
                float qq[4], kf[4], ef[8];
                *(float4*)&qq[0] = *(const float4*)&Qsm[kk * SS + si];
                *(float4*)&kf[0] = *(const float4*)&Ksm[kk * SS + sj];
                *(float4*)&ef[0] = *(const float4*)&ErT[kk * TS + tt];
                *(float4*)&ef[4] = *(const float4*)&ErT[kk * TS + tt + 4];
                #pragma unroll
                for (int a = 0; a < 4; a++) {
                    #pragma unroll
                    for (int c = 0; c < 4; c++) acc[a][c] += qq[a] * kf[c];
                    #pragma unroll
                    for (int c = 0; c < 8; c++) accT[a][c] += qq[a] * ef[c];
                }
            }
            #pragma unroll
            for (int a = 0; a < 4; a++) {
                #pragma unroll
                for (int c = 0; c < 4; c++)
                    Ssm[(sj + c) * SS + (si + a)] = acc[a][c];
                *(float4*)&Tsm[(si + a) * TS + tt]     = *(float4*)&accT[a][0];
                *(float4*)&Tsm[(si + a) * TS + tt + 4] = *(float4*)&accT[a][4];
            }
        }
        __syncthreads();

        // ---- combine + mask + online softmax (4 threads per row) ----
        {
            const int r   = tid >> 2;
            const int sub = tid & 3;
            const float mold = msm[r];
            float sv[16];
            float mx = -1e30f;
            #pragma unroll
            for (int n = 0; n < 16; n++) {
                const int j = sub * 16 + n;
                float s = (Ssm[j * SS + r] + Tsm[r * TS + (r - j + 63)]) * sc2;
                const bool valid = (kb < qb) || (j <= r);
                s = valid ? s : -1e30f;
                sv[n] = s;
                mx = fmaxf(mx, s);
            }
            mx = fmaxf(mx, __shfl_xor_sync(0xffffffffu, mx, 1));
            mx = fmaxf(mx, __shfl_xor_sync(0xffffffffu, mx, 2));
            const float mnew = fmaxf(mold, mx);
            float psum = 0.f;
            #pragma unroll
            for (int n = 0; n < 16; n++) {
                const int j = sub * 16 + n;
                const float p = exp2f(sv[n] - mnew);
                Ssm[j * SS + r] = p;   // in-place: S -> P
                psum += p;
            }
            psum += __shfl_xor_sync(0xffffffffu, psum, 1);
            psum += __shfl_xor_sync(0xffffffffu, psum, 2);
            if (sub == 0) {
                const float sc = exp2f(mold - mnew);
                rsc[r] = sc;
                msm[r] = mnew;
                lsm[r] = lsm[r] * sc + psum;
            }
        }
        __syncthreads();

        // ---- O rescale + PV accumulate ----
        {
            float rs[4];
            #pragma unroll
            for (int a = 0; a < 4; a++) rs[a] = rsc[si + a];
            #pragma unroll
            for (int a = 0; a < 4; a++)
                #pragma unroll
                for (int c = 0; c < 4; c++) O[a][c] *= rs[a];
            #pragma unroll 4
            for (int kk = 0; kk < 64; kk++) {
                float pp[4], vv[4];
                *(float4*)&pp[0] = *(const float4*)&Ssm[kk * SS + si];
                *(float4*)&vv[0] = *(const float4*)&Vsm[kk * SS + sj];
                #pragma unroll
                for (int a = 0; a < 4; a++)
                    #pragma unroll
                    for (int c = 0; c < 4; c++) O[a][c] += pp[a] * vv[c];
            }
        }
    }

    // Normalize and write out: Y[b, l, h*64 + d]
    #pragma unroll
    for (int a = 0; a < 4; a++) {
        const float inv = 1.0f / lsm[si + a];
        float4 o;
        o.x = O[a][0] * inv;
        o.y = O[a][1] * inv;
        o.z = O[a][2] * inv;
        o.w = O[a][3] * inv;
        *(float4*)&Y[(size_t)(b * LSEQ + l0 + si + a) * DMODEL + h * HSZ + sj] = o;
    }
}

// ---------------------------------------------------------------------------
// kernel_launch: qkv GEMM -> fused attention -> proj GEMM
// Inputs (metadata order): x, W_attn, b_attn, Er, W_proj, b_proj
// ---------------------------------------------------------------------------
extern "C" void kernel_launch(void* const* d_in, const int* in_sizes, int n_in,
                              void* d_out, int out_size)
{
    const float* x      = (const float*)d_in[0];
    const float* W_attn = (const float*)d_in[1];
    const float* b_attn = (const float*)d_in[2];
    const float* Er     = (const float*)d_in[3];
    const float* W_proj = (const float*)d_in[4];
    const float* b_proj = (const float*)d_in[5];
    float* out = (float*)d_out;

    void *qkv_p = nullptr, *y_p = nullptr;
    cudaGetSymbolAddress(&qkv_p, g_qkv);
    cudaGetSymbolAddress(&y_p, g_y);

    cudaFuncSetAttribute(attn_relpos_kernel,
                         cudaFuncAttributeMaxDynamicSharedMemorySize,
                         ATTN_SMEM_BYTES);

    // 1) qkv = x @ W_attn + b_attn        [8192,1024]x[1024,3072]
    sgemm_bias_kernel<<<dim3(3 * DMODEL / 128, MTOT / 128), 256>>>(
        x, W_attn, b_attn, (float*)qkv_p, MTOT, 3 * DMODEL, DMODEL);

    // 2) fused attention with rel-pos skew
    attn_relpos_kernel<<<BATCH * NHEAD * (LSEQ / 64), 256, ATTN_SMEM_BYTES>>>(
        (const float*)qkv_p, Er, (float*)y_p);

    // 3) out = y @ W_proj + b_proj        [8192,1024]x[1024,1024]
    sgemm_bias_kernel<<<dim3(DMODEL / 128, MTOT / 128), 256>>>(
        (const float*)y_p, W_proj, b_proj, out, MTOT, DMODEL, DMODEL);
}

// round 10
// speedup vs baseline: 3.0765x; 3.0765x over previous
#include <cuda_runtime.h>
#include <cuda_bf16.h>
#include <math.h>
#include <float.h>
#include <stdint.h>

// Problem constants
#define LSEQ   2048
#define DMODEL 1024
#define NHEAD  16
#define HSZ    64
#define BATCH  4
#define MTOT   (BATCH*LSEQ)      // 8192
#define KDIM   1024

// ---------------------------------------------------------------------------
// Scratch (device globals: allocation-free rule)
// ---------------------------------------------------------------------------
__device__ __nv_bfloat16 g_xhi[(size_t)MTOT * KDIM];
__device__ __nv_bfloat16 g_xlo[(size_t)MTOT * KDIM];
__device__ __nv_bfloat16 g_wthi[(size_t)3 * DMODEL * KDIM];
__device__ __nv_bfloat16 g_wtlo[(size_t)3 * DMODEL * KDIM];
__device__ __nv_bfloat16 g_qkvhi[(size_t)MTOT * 3 * DMODEL];
__device__ __nv_bfloat16 g_qkvlo[(size_t)MTOT * 3 * DMODEL];
__device__ __nv_bfloat16 g_erhi[(size_t)LSEQ * HSZ];
__device__ __nv_bfloat16 g_erlo[(size_t)LSEQ * HSZ];
__device__ __nv_bfloat16 g_yhi[(size_t)MTOT * DMODEL];
__device__ __nv_bfloat16 g_ylo[(size_t)MTOT * DMODEL];

// ---------------------------------------------------------------------------
// Helpers (compute_103-safe: mma.sync / ldmatrix / cp.async only)
// ---------------------------------------------------------------------------
__device__ __forceinline__ uint32_t smem_u32(const void* p) {
    uint32_t a;
    asm("{ .reg .u64 t; cvta.to.shared.u64 t, %1; cvt.u32.u64 %0, t; }"
        : "=r"(a) : "l"(p));
    return a;
}

#define CP_ASYNC16(dst, src) \
    asm volatile("cp.async.cg.shared.global [%0], [%1], 16;" :: "r"(dst), "l"(src))
#define CP_COMMIT() asm volatile("cp.async.commit_group;" ::: "memory")
#define CP_WAIT(n)  asm volatile("cp.async.wait_group %0;" :: "n"(n) : "memory")

__device__ __forceinline__ void cp16z(uint32_t dst, const void* src, bool ok) {
    int sz = ok ? 16 : 0;
    asm volatile("cp.async.cg.shared.global [%0], [%1], 16, %2;"
                 :: "r"(dst), "l"(src), "r"(sz));
}

__device__ __forceinline__ void ldsm4(uint32_t* r, uint32_t addr) {
    asm volatile("ldmatrix.sync.aligned.m8n8.x4.shared.b16 {%0,%1,%2,%3}, [%4];"
                 : "=r"(r[0]), "=r"(r[1]), "=r"(r[2]), "=r"(r[3]) : "r"(addr));
}

__device__ __forceinline__ void ldsm4t(uint32_t* r, uint32_t addr) {
    asm volatile("ldmatrix.sync.aligned.m8n8.x4.trans.shared.b16 {%0,%1,%2,%3}, [%4];"
                 : "=r"(r[0]), "=r"(r[1]), "=r"(r[2]), "=r"(r[3]) : "r"(addr));
}

__device__ __forceinline__ void mma16816(float* c, const uint32_t* a, const uint32_t* b) {
    asm volatile(
        "mma.sync.aligned.m16n8k16.row.col.f32.bf16.bf16.f32 "
        "{%0,%1,%2,%3}, {%4,%5,%6,%7}, {%8,%9}, {%0,%1,%2,%3};"
        : "+f"(c[0]), "+f"(c[1]), "+f"(c[2]), "+f"(c[3])
        : "r"(a[0]), "r"(a[1]), "r"(a[2]), "r"(a[3]), "r"(b[0]), "r"(b[1]));
}

__device__ __forceinline__ float ex2(float x) {
    float y;
    asm("ex2.approx.f32 %0, %1;" : "=f"(y) : "f"(x));
    return y;
}

__device__ __forceinline__ void split2(float v, unsigned short& h, unsigned short& l) {
    __nv_bfloat16 hb = __float2bfloat16(v);
    __nv_bfloat16 lb = __float2bfloat16(v - __bfloat162float(hb));
    h = __bfloat16_as_ushort(hb);
    l = __bfloat16_as_ushort(lb);
}

// ---------------------------------------------------------------------------
// Split fp32 -> bf16 (hi, lo).  n divisible by 1024.
// ---------------------------------------------------------------------------
__global__ __launch_bounds__(256) void split_bf16_kernel(
    const float* __restrict__ src, __nv_bfloat16* __restrict__ hi,
    __nv_bfloat16* __restrict__ lo, int n)
{
    int i = (blockIdx.x * 256 + threadIdx.x) * 4;
    if (i >= n) return;
    float4 v = *(const float4*)(src + i);
    ushort4 hv, lv;
    split2(v.x, hv.x, lv.x);
    split2(v.y, hv.y, lv.y);
    split2(v.z, hv.z, lv.z);
    split2(v.w, hv.w, lv.w);
    *(ushort4*)(hi + i) = hv;
    *(ushort4*)(lo + i) = lv;
}

// ---------------------------------------------------------------------------
// Transpose + split: W[K][N] fp32 -> Wt_hi[N][K], Wt_lo[N][K] bf16.
// ---------------------------------------------------------------------------
__global__ __launch_bounds__(256) void transpose_split_kernel(
    const float* __restrict__ W, __nv_bfloat16* __restrict__ Thi,
    __nv_bfloat16* __restrict__ Tlo, int K, int N)
{
    __shared__ float t[32][33];
    const int tx = threadIdx.x, ty = threadIdx.y;
    const int n0 = blockIdx.x * 32, k0 = blockIdx.y * 32;
    #pragma unroll
    for (int i = 0; i < 4; i++)
        t[ty + i * 8][tx] = W[(size_t)(k0 + ty + i * 8) * N + n0 + tx];
    __syncthreads();
    #pragma unroll
    for (int i = 0; i < 4; i++) {
        float v = t[tx][ty + i * 8];
        unsigned short h, l;
        split2(v, h, l);
        size_t o = (size_t)(n0 + ty + i * 8) * K + k0 + tx;
        Thi[o] = __ushort_as_bfloat16(h);
        Tlo[o] = __ushort_as_bfloat16(l);
    }
}

// ---------------------------------------------------------------------------
// HMMA bf16-split GEMM: C[M,Ntot] = A[M,1024] @ Bt[Ntot,1024]^T + bias
// 128x128 CTA tile, 8 warps (64x32 each), K-chunk 32, cp.async double buffer.
// 3 passes per k-step: hi*hi + hi*lo + lo*hi.
// out: fp32 C  OR  bf16 hi/lo pair (bf16out != 0).
// ---------------------------------------------------------------------------
#define GM_NCH 32
#define GM_ROWB 80
#define GM_ARR (128 * GM_ROWB)
#define GM_STAGE (4 * GM_ARR)
#define GM_SMEM (2 * GM_STAGE)

__global__ __launch_bounds__(256, 2) void gemm_mma_kernel(
    const __nv_bfloat16* __restrict__ Ahi, const __nv_bfloat16* __restrict__ Alo,
    const __nv_bfloat16* __restrict__ Bhi, const __nv_bfloat16* __restrict__ Blo,
    const float* __restrict__ bias, float* __restrict__ C, int Ntot,
    __nv_bfloat16* __restrict__ Chi, __nv_bfloat16* __restrict__ Clo, int bf16out)
{
    extern __shared__ char smem[];
    const uint32_t sb = smem_u32(smem);
    const int tid = threadIdx.x;
    const int wid = tid >> 5;
    const int lane = tid & 31;
    const int warp_m = wid >> 2;
    const int warp_n = wid & 3;
    const int row0 = blockIdx.y * 128;
    const int col0 = blockIdx.x * 128;

    float acc[16][4];
    #pragma unroll
    for (int i = 0; i < 16; i++)
        #pragma unroll
        for (int j = 0; j < 4; j++) acc[i][j] = 0.f;

    const int arow = warp_m * 64 + (lane & 15);
    const int acb  = (lane >> 4);
    const int brow = warp_n * 32 + ((lane >> 4) & 1) * 8 + (lane & 7);
    const int bcb  = ((lane >> 3) & 1);

    auto prefetch = [&](int stage, int c) {
        const int k0 = c * 32;
        #pragma unroll
        for (int i = 0; i < 8; i++) {
            const int arr = i >> 1;
            const int rem = ((i & 1) << 8) + tid;
            const int r = rem >> 2;
            const int cb = rem & 3;
            const uint32_t dst = sb + stage * GM_STAGE + arr * GM_ARR
                               + r * GM_ROWB + cb * 16;
            const __nv_bfloat16* base =
                (arr == 0) ? Ahi : (arr == 1) ? Alo : (arr == 2) ? Bhi : Blo;
            const int grow = ((arr < 2) ? row0 : col0) + r;
            const void* src = base + (size_t)grow * KDIM + k0 + cb * 8;
            CP_ASYNC16(dst, src);
        }
    };

    prefetch(0, 0);
    CP_COMMIT();

    for (int c = 0; c < GM_NCH; c++) {
        if (c + 1 < GM_NCH) {
            prefetch((c + 1) & 1, c + 1);
            CP_COMMIT();
            CP_WAIT(1);
        } else {
            CP_WAIT(0);
        }
        __syncthreads();

        const uint32_t st = sb + (c & 1) * GM_STAGE;
        const uint32_t ahB = st;
        const uint32_t alB = st + GM_ARR;
        const uint32_t bhB = st + 2 * GM_ARR;
        const uint32_t blB = st + 3 * GM_ARR;

        #pragma unroll
        for (int ks = 0; ks < 2; ks++) {
            const int kcb = acb + 2 * ks;
            const int kbb = bcb + 2 * ks;
            uint32_t af[4][4], bh[2][4], bl[2][4];

            #pragma unroll
            for (int mt = 0; mt < 4; mt++)
                ldsm4(af[mt], ahB + (arow + mt * 16) * GM_ROWB + kcb * 16);
            #pragma unroll
            for (int p = 0; p < 2; p++)
                ldsm4(bh[p], bhB + (brow + p * 16) * GM_ROWB + kbb * 16);

            #pragma unroll
            for (int mt = 0; mt < 4; mt++)
                #pragma unroll
                for (int nt = 0; nt < 4; nt++)
                    mma16816(acc[mt * 4 + nt], af[mt], &bh[nt >> 1][(nt & 1) * 2]);

            #pragma unroll
            for (int p = 0; p < 2; p++)
                ldsm4(bl[p], blB + (brow + p * 16) * GM_ROWB + kbb * 16);

            #pragma unroll
            for (int mt = 0; mt < 4; mt++)
                #pragma unroll
                for (int nt = 0; nt < 4; nt++)
                    mma16816(acc[mt * 4 + nt], af[mt], &bl[nt >> 1][(nt & 1) * 2]);

            #pragma unroll
            for (int mt = 0; mt < 4; mt++)
                ldsm4(af[mt], alB + (arow + mt * 16) * GM_ROWB + kcb * 16);

            #pragma unroll
            for (int mt = 0; mt < 4; mt++)
                #pragma unroll
                for (int nt = 0; nt < 4; nt++)
                    mma16816(acc[mt * 4 + nt], af[mt], &bh[nt >> 1][(nt & 1) * 2]);
        }
        __syncthreads();
    }

    #pragma unroll
    for (int mt = 0; mt < 4; mt++) {
        const int row = row0 + warp_m * 64 + mt * 16 + (lane >> 2);
        #pragma unroll
        for (int nt = 0; nt < 4; nt++) {
            const int col = col0 + warp_n * 32 + nt * 8 + 2 * (lane & 3);
            const float b0 = bias[col], b1 = bias[col + 1];
            float* c = acc[mt * 4 + nt];
            float v0 = c[0] + b0, v1 = c[1] + b1;
            float v2 = c[2] + b0, v3 = c[3] + b1;
            if (!bf16out) {
                *(float2*)(C + (size_t)row * Ntot + col) = make_float2(v0, v1);
                *(float2*)(C + (size_t)(row + 8) * Ntot + col) = make_float2(v2, v3);
            } else {
                ushort2 h0, l0p, h1, l1p;
                split2(v0, h0.x, l0p.x); split2(v1, h0.y, l0p.y);
                split2(v2, h1.x, l1p.x); split2(v3, h1.y, l1p.y);
                size_t o0 = (size_t)row * Ntot + col;
                size_t o1 = (size_t)(row + 8) * Ntot + col;
                *(ushort2*)(Chi + o0) = h0; *(ushort2*)(Clo + o0) = l0p;
                *(ushort2*)(Chi + o1) = h1; *(ushort2*)(Clo + o1) = l1p;
            }
        }
    }
}

// ---------------------------------------------------------------------------
// HMMA flash attention with rel-pos skew.
// Per CTA: (b,h,qb) -> 64 queries. Per key tile:
//   U = Q @ [K ; ErBand]^T  (M=64, N=192, K=64), bf16 hi/lo 3-pass
//   softmax (base-2, ex2.approx) reading U from smem, P -> bf16 hi/lo
//   O += P @ V  (ldmatrix.trans B-path), 3-pass
// ---------------------------------------------------------------------------
#define AT_RS 144      // bf16 row stride bytes (64 data bf16 + 8 pad)
#define AT_US 196      // U row stride (floats)
#define O_QH 0
#define O_QL (O_QH + 64*AT_RS)
#define O_BH (O_QL + 64*AT_RS)
#define O_BL (O_BH + 192*AT_RS)
#define O_VH (O_BL + 192*AT_RS)
#define O_VL (O_VH + 64*AT_RS)
#define O_PH (O_VL + 64*AT_RS)
#define O_PL (O_PH + 64*AT_RS)
#define O_U  (O_PL + 64*AT_RS)
#define O_M  (O_U + 64*AT_US*4)
#define O_L  (O_M + 256)
#define O_R  (O_L + 256)
#define AT_SMEM (O_R + 256)   // 161536 bytes

__global__ __launch_bounds__(256, 1) void attn_mma_kernel(
    const __nv_bfloat16* __restrict__ qkvh, const __nv_bfloat16* __restrict__ qkvl,
    const __nv_bfloat16* __restrict__ erh,  const __nv_bfloat16* __restrict__ erl,
    __nv_bfloat16* __restrict__ Yh, __nv_bfloat16* __restrict__ Yl)
{
    extern __shared__ char smem[];
    const uint32_t sb = smem_u32(smem);
    float* Usm = (float*)(smem + O_U);
    float* msm = (float*)(smem + O_M);
    float* lsm = (float*)(smem + O_L);
    float* rsc = (float*)(smem + O_R);

    const int tid = threadIdx.x;
    const int lane = tid & 31;
    const int wid = tid >> 5;
    const int warp_m = wid >> 2, warp_n = wid & 3;
    const int qb = blockIdx.x & 31;
    const int h  = (blockIdx.x >> 5) & 15;
    const int b  = blockIdx.x >> 9;
    const int l0 = qb * 64;
    const size_t rowbase = (size_t)(b * LSEQ);

    // Q tile hi/lo -> smem (512 chunks per array)
    #pragma unroll
    for (int it = 0; it < 4; it++) {
        int id = tid + it * 256;
        int arr = id >> 9, rem = id & 511;
        int r = rem >> 3, u = rem & 7;
        const __nv_bfloat16* s = (arr ? qkvl : qkvh)
            + (rowbase + l0 + r) * 3072 + h * HSZ + u * 8;
        CP_ASYNC16(sb + (arr ? O_QL : O_QH) + r * AT_RS + u * 16, s);
    }
    CP_COMMIT();
    if (tid < 64) { msm[tid] = -1e30f; lsm[tid] = 0.f; }

    float O[2][2][4];
    #pragma unroll
    for (int a = 0; a < 2; a++)
        #pragma unroll
        for (int c = 0; c < 2; c++)
            #pragma unroll
            for (int q = 0; q < 4; q++) O[a][c][q] = 0.f;

    const int arow = warp_m * 32 + (lane & 15);
    const int acb  = lane >> 4;
    const int brow = warp_n * 48 + ((lane >> 4) & 1) * 8 + (lane & 7);
    const int bcb  = (lane >> 3) & 1;
    const int vrow = lane & 15;
    const int vcol = warp_n * 32 + (lane >> 4) * 16;

    const float sc2 = 0.125f * 1.4426950408889634f;

    for (int kb = 0; kb <= qb; kb++) {
        const int m0 = kb * 64;
        const int d0 = l0 - m0;
        __syncthreads();

        // K, V, ErBand tile loads (hi+lo) via cp.async
        #pragma unroll
        for (int it = 0; it < 16; it++) {
            if (it < 4) {
                int id = tid + it * 256;
                int arr = id >> 9, rem = id & 511;
                int r = rem >> 3, u = rem & 7;
                const __nv_bfloat16* s = (arr ? qkvl : qkvh)
                    + (rowbase + m0 + r) * 3072 + DMODEL + h * HSZ + u * 8;
                CP_ASYNC16(sb + (arr ? O_BL : O_BH) + r * AT_RS + u * 16, s);
            } else if (it < 8) {
                int id = tid + (it - 4) * 256;
                int arr = id >> 9, rem = id & 511;
                int r = rem >> 3, u = rem & 7;
                const __nv_bfloat16* s = (arr ? qkvl : qkvh)
                    + (rowbase + m0 + r) * 3072 + 2 * DMODEL + h * HSZ + u * 8;
                CP_ASYNC16(sb + (arr ? O_VL : O_VH) + r * AT_RS + u * 16, s);
            } else {
                int id = tid + (it - 8) * 256;
                int arr = id >> 10, rem = id & 1023;
                int t = rem >> 3, u = rem & 7;
                int g = (LSEQ + 62 - d0) - t;
                bool ok = (t < 127) && (g >= 0) && (g < LSEQ);
                const __nv_bfloat16* s = (arr ? erl : erh)
                    + (ok ? (size_t)g * HSZ : 0) + u * 8;
                cp16z(sb + (arr ? O_BL : O_BH) + (64 + t) * AT_RS + u * 16, s, ok);
            }
        }
        CP_COMMIT();
        CP_WAIT(0);
        __syncthreads();

        // ---- U = Q @ [K;ErB]^T : 3-pass hi/lo ----
        {
            float u[12][4];
            #pragma unroll
            for (int i = 0; i < 12; i++)
                #pragma unroll
                for (int q = 0; q < 4; q++) u[i][q] = 0.f;

            #pragma unroll
            for (int ks = 0; ks < 4; ks++) {
                uint32_t af[2][4], bhf[3][4], blf[3][4];
                #pragma unroll
                for (int mt = 0; mt < 2; mt++)
                    ldsm4(af[mt], sb + O_QH + (arow + mt * 16) * AT_RS + (acb + 2 * ks) * 16);
                #pragma unroll
                for (int p = 0; p < 3; p++)
                    ldsm4(bhf[p], sb + O_BH + (brow + p * 16) * AT_RS + (bcb + 2 * ks) * 16);
                #pragma unroll
                for (int mt = 0; mt < 2; mt++)
                    #pragma unroll
                    for (int nt = 0; nt < 6; nt++)
                        mma16816(u[mt * 6 + nt], af[mt], &bhf[nt >> 1][(nt & 1) * 2]);
                #pragma unroll
                for (int p = 0; p < 3; p++)
                    ldsm4(blf[p], sb + O_BL + (brow + p * 16) * AT_RS + (bcb + 2 * ks) * 16);
                #pragma unroll
                for (int mt = 0; mt < 2; mt++)
                    #pragma unroll
                    for (int nt = 0; nt < 6; nt++)
                        mma16816(u[mt * 6 + nt], af[mt], &blf[nt >> 1][(nt & 1) * 2]);
                #pragma unroll
                for (int mt = 0; mt < 2; mt++)
                    ldsm4(af[mt], sb + O_QL + (arow + mt * 16) * AT_RS + (acb + 2 * ks) * 16);
                #pragma unroll
                for (int mt = 0; mt < 2; mt++)
                    #pragma unroll
                    for (int nt = 0; nt < 6; nt++)
                        mma16816(u[mt * 6 + nt], af[mt], &bhf[nt >> 1][(nt & 1) * 2]);
            }
            #pragma unroll
            for (int mt = 0; mt < 2; mt++) {
                int row = warp_m * 32 + mt * 16 + (lane >> 2);
                #pragma unroll
                for (int nt = 0; nt < 6; nt++) {
                    int col = warp_n * 48 + nt * 8 + 2 * (lane & 3);
                    float* up = &Usm[row * AT_US + col];
                    *(float2*)up = make_float2(u[mt * 6 + nt][0], u[mt * 6 + nt][1]);
                    *(float2*)(up + 8 * AT_US) = make_float2(u[mt * 6 + nt][2], u[mt * 6 + nt][3]);
                }
            }
        }
        __syncthreads();

        // ---- online softmax; write P hi/lo ----
        {
            const int r = tid >> 2, sub = tid & 3;
            const float mold = msm[r];
            const float* ur = &Usm[r * AT_US];
            float sv[16], mx = -1e30f;
            #pragma unroll
            for (int n = 0; n < 16; n++) {
                int j = sub * 16 + n;
                float s = (ur[j] + ur[r - j + 127]) * sc2;
                bool valid = (kb < qb) || (j <= r);
                s = valid ? s : -1e30f;
                sv[n] = s;
                mx = fmaxf(mx, s);
            }
            mx = fmaxf(mx, __shfl_xor_sync(0xffffffffu, mx, 1));
            mx = fmaxf(mx, __shfl_xor_sync(0xffffffffu, mx, 2));
            const float mnew = fmaxf(mold, mx);
            float ps = 0.f;
            #pragma unroll
            for (int n = 0; n < 16; n++) {
                int j = sub * 16 + n;
                float p = ex2(sv[n] - mnew);
                ps += p;
                unsigned short ph, pl;
                split2(p, ph, pl);
                *(unsigned short*)(smem + O_PH + r * AT_RS + 2 * j) = ph;
                *(unsigned short*)(smem + O_PL + r * AT_RS + 2 * j) = pl;
            }
            ps += __shfl_xor_sync(0xffffffffu, ps, 1);
            ps += __shfl_xor_sync(0xffffffffu, ps, 2);
            if (sub == 0) {
                float sc = ex2(mold - mnew);
                rsc[r] = sc;
                msm[r] = mnew;
                lsm[r] = lsm[r] * sc + ps;
            }
        }
        __syncthreads();

        // ---- O rescale + PV (3-pass) ----
        {
            #pragma unroll
            for (int mt = 0; mt < 2; mt++) {
                int row = warp_m * 32 + mt * 16 + (lane >> 2);
                float rs0 = rsc[row], rs1 = rsc[row + 8];
                #pragma unroll
                for (int nt = 0; nt < 2; nt++) {
                    O[mt][nt][0] *= rs0; O[mt][nt][1] *= rs0;
                    O[mt][nt][2] *= rs1; O[mt][nt][3] *= rs1;
                }
            }
            #pragma unroll
            for (int ks = 0; ks < 4; ks++) {
                uint32_t pf[2][4], vhf[4], vlf[4];
                #pragma unroll
                for (int mt = 0; mt < 2; mt++)
                    ldsm4(pf[mt], sb + O_PH + (arow + mt * 16) * AT_RS + (acb + 2 * ks) * 16);
                ldsm4t(vhf, sb + O_VH + (ks * 16 + vrow) * AT_RS + vcol);
                #pragma unroll
                for (int mt = 0; mt < 2; mt++)
                    #pragma unroll
                    for (int nt = 0; nt < 2; nt++)
                        mma16816(O[mt][nt], pf[mt], &vhf[nt * 2]);
                ldsm4t(vlf, sb + O_VL + (ks * 16 + vrow) * AT_RS + vcol);
                #pragma unroll
                for (int mt = 0; mt < 2; mt++)
                    #pragma unroll
                    for (int nt = 0; nt < 2; nt++)
                        mma16816(O[mt][nt], pf[mt], &vlf[nt * 2]);
                #pragma unroll
                for (int mt = 0; mt < 2; mt++)
                    ldsm4(pf[mt], sb + O_PL + (arow + mt * 16) * AT_RS + (acb + 2 * ks) * 16);
                #pragma unroll
                for (int mt = 0; mt < 2; mt++)
                    #pragma unroll
                    for (int nt = 0; nt < 2; nt++)
                        mma16816(O[mt][nt], pf[mt], &vhf[nt * 2]);
            }
        }
    }

    // ---- normalize + write y hi/lo ----
    #pragma unroll
    for (int mt = 0; mt < 2; mt++) {
        int row = warp_m * 32 + mt * 16 + (lane >> 2);
        #pragma unroll
        for (int half = 0; half < 2; half++) {
            int rr = row + half * 8;
            float inv = 1.0f / lsm[rr];
            #pragma unroll
            for (int nt = 0; nt < 2; nt++) {
                int d = warp_n * 16 + nt * 8 + 2 * (lane & 3);
                float v0 = O[mt][nt][half * 2 + 0] * inv;
                float v1 = O[mt][nt][half * 2 + 1] * inv;
                ushort2 hv, lv;
                split2(v0, hv.x, lv.x);
                split2(v1, hv.y, lv.y);
                size_t off = (rowbase + l0 + rr) * DMODEL + h * HSZ + d;
                *(ushort2*)(Yh + off) = hv;
                *(ushort2*)(Yl + off) = lv;
            }
        }
    }
}

// ---------------------------------------------------------------------------
// kernel_launch
// Inputs (metadata order): x, W_attn, b_attn, Er, W_proj, b_proj
// ---------------------------------------------------------------------------
extern "C" void kernel_launch(void* const* d_in, const int* in_sizes, int n_in,
                              void* d_out, int out_size)
{
    const float* x      = (const float*)d_in[0];
    const float* W_attn = (const float*)d_in[1];
    const float* b_attn = (const float*)d_in[2];
    const float* Er     = (const float*)d_in[3];
    const float* W_proj = (const float*)d_in[4];
    const float* b_proj = (const float*)d_in[5];
    float* out = (float*)d_out;

    void *p_xhi, *p_xlo, *p_wthi, *p_wtlo, *p_qh, *p_ql, *p_eh, *p_el, *p_yh, *p_yl;
    cudaGetSymbolAddress(&p_xhi, g_xhi);
    cudaGetSymbolAddress(&p_xlo, g_xlo);
    cudaGetSymbolAddress(&p_wthi, g_wthi);
    cudaGetSymbolAddress(&p_wtlo, g_wtlo);
    cudaGetSymbolAddress(&p_qh, g_qkvhi);
    cudaGetSymbolAddress(&p_ql, g_qkvlo);
    cudaGetSymbolAddress(&p_eh, g_erhi);
    cudaGetSymbolAddress(&p_el, g_erlo);
    cudaGetSymbolAddress(&p_yh, g_yhi);
    cudaGetSymbolAddress(&p_yl, g_ylo);
    __nv_bfloat16* xhi = (__nv_bfloat16*)p_xhi;
    __nv_bfloat16* xlo = (__nv_bfloat16*)p_xlo;
    __nv_bfloat16* wthi = (__nv_bfloat16*)p_wthi;
    __nv_bfloat16* wtlo = (__nv_bfloat16*)p_wtlo;
    __nv_bfloat16* qh = (__nv_bfloat16*)p_qh;
    __nv_bfloat16* ql = (__nv_bfloat16*)p_ql;
    __nv_bfloat16* eh = (__nv_bfloat16*)p_eh;
    __nv_bfloat16* el = (__nv_bfloat16*)p_el;
    __nv_bfloat16* yh = (__nv_bfloat16*)p_yh;
    __nv_bfloat16* yl = (__nv_bfloat16*)p_yl;

    cudaFuncSetAttribute(gemm_mma_kernel,
                         cudaFuncAttributeMaxDynamicSharedMemorySize, GM_SMEM);
    cudaFuncSetAttribute(attn_mma_kernel,
                         cudaFuncAttributeMaxDynamicSharedMemorySize, AT_SMEM);

    // 1) weight/input prep
    transpose_split_kernel<<<dim3(3 * DMODEL / 32, KDIM / 32), dim3(32, 8)>>>(
        W_attn, wthi, wtlo, KDIM, 3 * DMODEL);
    split_bf16_kernel<<<(MTOT * KDIM) / 1024, 256>>>(x, xhi, xlo, MTOT * KDIM);
    split_bf16_kernel<<<(LSEQ * HSZ) / 1024, 256>>>(Er, eh, el, LSEQ * HSZ);

    // 2) qkv = x @ W_attn + b_attn -> bf16 hi/lo
    gemm_mma_kernel<<<dim3(3 * DMODEL / 128, MTOT / 128), 256, GM_SMEM>>>(
        xhi, xlo, wthi, wtlo, b_attn, nullptr, 3 * DMODEL, qh, ql, 1);

    // 3) attention -> y bf16 hi/lo
    attn_mma_kernel<<<BATCH * NHEAD * (LSEQ / 64), 256, AT_SMEM>>>(
        qh, ql, eh, el, yh, yl);

    // 4) proj
    transpose_split_kernel<<<dim3(DMODEL / 32, KDIM / 32), dim3(32, 8)>>>(
        W_proj, wthi, wtlo, KDIM, DMODEL);
    gemm_mma_kernel<<<dim3(DMODEL / 128, MTOT / 128), 256, GM_SMEM>>>(
        yh, yl, wthi, wtlo, b_proj, out, DMODEL, nullptr, nullptr, 0);
}